// round 4
// baseline (speedup 1.0000x reference)
#include <cuda_runtime.h>
#include <cstdint>

#define BN 64
#define PP 8732
#define CC 81
#define KT 16
#define THRESH 0.5f
#define VAR0 0.1f
#define VAR1 0.2f

#define ROWS 128
#define TILES 69                 // ceil(PP/ROWS)
#define TOT_TILES (BN * TILES)   // 4416
#define NCE 296                  // persistent CE blocks (2 per SM)
#define NCH 16
#define CHUNK 546
#define MBLK (BN * NCH)          // 1024 matchA blocks
#define TPB_POST 512
#define PPAD 9216                // 512*18, uniform loop bound

// ---------------- scratch ----------------
__device__ float g_bto[BN * PP];
__device__ int   g_bti[BN * PP];
__device__ float g_lse[BN * PP];
__device__ float g_lm[BN * PP];
__device__ unsigned long long g_best[BN * KT];   // idempotent atomicMax accumulator
__device__ float g_loss_l[BN];
__device__ float g_loss_c[BN];
__device__ int   g_num_pos[BN];

// ---------------- PTX helpers ----------------
static __device__ __forceinline__ unsigned su32(const void* p) {
    return (unsigned)__cvta_generic_to_shared(p);
}
#define MBAR_INIT(a, c) \
    asm volatile("mbarrier.init.shared.b64 [%0], %1;" :: "r"(a), "r"(c) : "memory")
#define MBAR_EXPECT(a, n) \
    asm volatile("mbarrier.arrive.expect_tx.shared.b64 _, [%0], %1;" :: "r"(a), "r"(n) : "memory")
#define BULK_G2S(dst, src, n, mbar) \
    asm volatile("cp.async.bulk.shared::cta.global.mbarrier::complete_tx::bytes [%0], [%1], %2, [%3];" \
                 :: "r"(dst), "l"(src), "r"(n), "r"(mbar) : "memory")
#define MBAR_WAITP(a, par) do {                                                     \
    unsigned _done = 0;                                                             \
    while (!_done) {                                                                \
        asm volatile("{\n\t.reg .pred p;\n\t"                                       \
            "mbarrier.try_wait.parity.acquire.cta.shared::cta.b64 p, [%1], %2, 0x989680;\n\t" \
            "selp.b32 %0, 1, 0, p;\n\t}"                                            \
            : "=r"(_done) : "r"(a), "r"((unsigned)(par)) : "memory");               \
    }                                                                               \
} while (0)

// ---------------- kernel 1: persistent CE pipeline + matchA ----------------
extern __shared__ float dynbuf[];   // CE role: 2 * ROWS * CC floats

__global__ __launch_bounds__(128, 4) void k_big(const float* __restrict__ conf,
                                                const float* __restrict__ priors,
                                                const float* __restrict__ targets) {
    __shared__ float s_t[KT][4];
    __shared__ float s_area[KT];
    __shared__ unsigned long long s_best[KT];
    __shared__ __align__(8) unsigned long long s_mbar[2];

    const int blk = blockIdx.x;
    const int tid = threadIdx.x;

    if (blk < NCE) {
        // ------- persistent CE role -------
        const unsigned mb0 = su32(&s_mbar[0]);
        const unsigned mb1 = su32(&s_mbar[1]);
        if (tid == 0) { MBAR_INIT(mb0, 1); MBAR_INIT(mb1, 1); }
        __syncthreads();

        const int nT = (TOT_TILES - blk + NCE - 1) / NCE;

        // prologue: prefetch up to 2 tiles
        if (tid == 0) {
#pragma unroll
            for (int i = 0; i < 2; i++) {
                if (i < nT) {
                    const int t = blk + i * NCE;
                    const int bb = t / TILES;
                    const int r0 = (t - bb * TILES) * ROWS;
                    const int nv = (r0 + ROWS <= PP) ? ROWS : PP - r0;
                    const unsigned nb = (unsigned)(nv * CC * 4);
                    const unsigned mb = i ? mb1 : mb0;
                    MBAR_EXPECT(mb, nb);
                    BULK_G2S(su32(dynbuf + i * (ROWS * CC)),
                             conf + ((size_t)bb * PP + r0) * CC, nb, mb);
                }
            }
        }

        for (int it = 0; it < nT; it++) {
            const int st = it & 1;
            MBAR_WAITP(st ? mb1 : mb0, (it >> 1) & 1);

            const int t = blk + it * NCE;
            const int bb = t / TILES;
            const int r0 = (t - bb * TILES) * ROWS;
            const int nv = (r0 + ROWS <= PP) ? ROWS : PP - r0;

            if (tid < nv) {
                const float* row = dynbuf + st * (ROWS * CC) + tid * CC;
                float s0 = 0.0f, s1 = 0.0f, s2 = 0.0f, s3 = 0.0f;
#pragma unroll 5
                for (int i = 0; i + 3 < CC; i += 4) {
                    s0 += __expf(row[i]);
                    s1 += __expf(row[i + 1]);
                    s2 += __expf(row[i + 2]);
                    s3 += __expf(row[i + 3]);
                }
                s0 += __expf(row[CC - 1]);
                const float lse = __logf((s0 + s1) + (s2 + s3));
                const int idx = bb * PP + r0 + tid;
                g_lse[idx] = lse;
                g_lm[idx] = lse - row[0];
            }
            __syncthreads();   // all reads of buf[st] complete before reissue

            if (tid == 0 && it + 2 < nT) {
                const int t2 = blk + (it + 2) * NCE;
                const int bb2 = t2 / TILES;
                const int r02 = (t2 - bb2 * TILES) * ROWS;
                const int nv2 = (r02 + ROWS <= PP) ? ROWS : PP - r02;
                const unsigned nb2 = (unsigned)(nv2 * CC * 4);
                const unsigned mb = st ? mb1 : mb0;
                MBAR_EXPECT(mb, nb2);
                BULK_G2S(su32(dynbuf + st * (ROWS * CC)),
                         conf + ((size_t)bb2 * PP + r02) * CC, nb2, mb);
            }
        }
    } else {
        // ------- matchA role -------
        const int q = blk - NCE;
        const int b = q >> 4;
        const int c = q & 15;
        if (tid < KT) {
            const float* tg = targets + (size_t)(b * KT + tid) * 6;
            s_t[tid][0] = tg[2]; s_t[tid][1] = tg[3];
            s_t[tid][2] = tg[4]; s_t[tid][3] = tg[5];
            s_area[tid] = (tg[4] - tg[2]) * (tg[5] - tg[3]);
            s_best[tid] = 0ull;
        }
        __syncthreads();

        const int p0 = c * CHUNK;
        const int p1 = (p0 + CHUNK < PP) ? p0 + CHUNK : PP;

        float bk_ov[KT];
        int   bk_p[KT];
#pragma unroll
        for (int k = 0; k < KT; k++) { bk_ov[k] = -1.0f; bk_p[k] = 0; }

        for (int p = p0 + tid; p < p1; p += 128) {
            const float4 pr = ((const float4*)priors)[p];
            const float parea = (pr.z - pr.x) * (pr.w - pr.y);
            float bestov = -1.0f;
            int besti = 0;
#pragma unroll
            for (int k = 0; k < KT; k++) {
                float ix = fminf(s_t[k][2], pr.z) - fmaxf(s_t[k][0], pr.x);
                float iy = fminf(s_t[k][3], pr.w) - fmaxf(s_t[k][1], pr.y);
                float inter = fmaxf(ix, 0.0f) * fmaxf(iy, 0.0f);
                float ov = inter / (s_area[k] + parea - inter);
                if (ov > bestov) { bestov = ov; besti = k; }
                if (ov > bk_ov[k]) { bk_ov[k] = ov; bk_p[k] = p; }
            }
            g_bto[b * PP + p] = bestov;
            g_bti[b * PP + p] = besti;
        }
#pragma unroll
        for (int k = 0; k < KT; k++) {
            unsigned long long key =
                ((unsigned long long)__float_as_uint(bk_ov[k]) << 32) |
                (unsigned long long)(0xFFFFFFFFu - (unsigned)bk_p[k]);
            atomicMax(&s_best[k], key);
        }
        __syncthreads();
        if (tid < KT)
            atomicMax(&g_best[b * KT + tid], s_best[tid]);
    }
}

// ---------------- kernel 2: force-assign + smooth-L1 + pos-CE + topk ----------------
__global__ __launch_bounds__(TPB_POST) void k_post(const float* __restrict__ conf,
                                                   const float* __restrict__ loc,
                                                   const float* __restrict__ priors,
                                                   const float* __restrict__ targets) {
    const int b = blockIdx.x;
    const int tid = threadIdx.x;
    const int lane = tid & 31;
    const int bPP = b * PP;

    __shared__ __align__(16) float s_lm[PP];
    __shared__ int s_hist[256];
    __shared__ int s_cum[256];
    __shared__ float s_redf[TPB_POST];
    __shared__ int s_redi[TPB_POST];
    __shared__ float s_t[KT][4];
    __shared__ int s_lab[KT];
    __shared__ unsigned s_prefix;
    __shared__ int s_rem;
    __shared__ float s_spos;
    __shared__ __align__(8) unsigned long long s_mbar;

    const unsigned mb = su32(&s_mbar);
    if (tid == 0) MBAR_INIT(mb, 1);
    if (tid < KT) {
        const float* tg = targets + (size_t)(b * KT + tid) * 6;
        s_lab[tid] = (int)tg[1];
        s_t[tid][0] = tg[2]; s_t[tid][1] = tg[3];
        s_t[tid][2] = tg[4]; s_t[tid][3] = tg[5];
    }
    __syncthreads();
    if (tid == 0) {
        MBAR_EXPECT(mb, (unsigned)(PP * 4));
        BULK_G2S(su32(s_lm), g_lm + bPP, (unsigned)(PP * 4), mb);
        for (int k = 0; k < KT; k++) {   // sequential force-assign, last write wins
            unsigned long long key = g_best[b * KT + k];
            int p = (int)(0xFFFFFFFFu - (unsigned)(key & 0xFFFFFFFFull));
            g_bti[bPP + p] = k;
            g_bto[bPP + p] = __uint_as_float((unsigned)(key >> 32));
        }
    }
    __syncthreads();
    MBAR_WAITP(mb, 0);

    // main pass
    float lsum = 0.0f, spos = 0.0f;
    int cnt = 0;
    for (int p = tid; p < PP; p += TPB_POST) {
        const float ov = g_bto[bPP + p];
        const int k = g_bti[bPP + p];
        const int ct = (ov < THRESH) ? 0 : s_lab[k];
        if (ct > 0) {
            cnt++;
            s_lm[p] = 0.0f;
            spos += g_lse[bPP + p] - conf[(size_t)(bPP + p) * CC + ct];
            const float4 pr = ((const float4*)priors)[p];
            const float pcx = 0.5f * (pr.x + pr.z), pcy = 0.5f * (pr.y + pr.w);
            const float pw = pr.z - pr.x, ph = pr.w - pr.y;
            const float mx1 = s_t[k][0], my1 = s_t[k][1];
            const float mx2 = s_t[k][2], my2 = s_t[k][3];
            float g0 = (0.5f * (mx1 + mx2) - pcx) / (VAR0 * pw);
            float g1 = (0.5f * (my1 + my2) - pcy) / (VAR0 * ph);
            float g2 = logf((mx2 - mx1) / pw) / VAR1;
            float g3 = logf((my2 - my1) / ph) / VAR1;
            const float4 ld = ((const float4*)loc)[bPP + p];
            float d, ad;
            d = ld.x - g0; ad = fabsf(d); lsum += (ad < 1.0f) ? 0.5f * d * d : ad - 0.5f;
            d = ld.y - g1; ad = fabsf(d); lsum += (ad < 1.0f) ? 0.5f * d * d : ad - 0.5f;
            d = ld.z - g2; ad = fabsf(d); lsum += (ad < 1.0f) ? 0.5f * d * d : ad - 0.5f;
            d = ld.w - g3; ad = fabsf(d); lsum += (ad < 1.0f) ? 0.5f * d * d : ad - 0.5f;
        }
    }
    s_redi[tid] = cnt;
    s_redf[tid] = spos;
    __syncthreads();
    for (int s = TPB_POST / 2; s > 0; s >>= 1) {
        if (tid < s) { s_redi[tid] += s_redi[tid + s]; s_redf[tid] += s_redf[tid + s]; }
        __syncthreads();
    }
    const int npos = s_redi[0];
    if (tid == 0) s_spos = s_redf[0];
    __syncthreads();
    s_redf[tid] = lsum;
    __syncthreads();
    for (int s = TPB_POST / 2; s > 0; s >>= 1) {
        if (tid < s) s_redf[tid] += s_redf[tid + s];
        __syncthreads();
    }
    if (tid == 0) {
        g_loss_l[b] = s_redf[0];
        g_num_pos[b] = npos;
    }

    int k = 3 * npos;
    if (k > PP - 1) k = PP - 1;

    float T = 0.0f;
    if (k > 0) {
        if (tid == 0) { s_prefix = 0u; s_rem = k; }
        if (tid < 256) s_hist[tid] = 0;
        __syncthreads();
        for (int shift = 24; shift >= 0; shift -= 8) {
            const unsigned pref = s_prefix;
            const int rem = s_rem;
            const unsigned hm = (shift == 24) ? 0u : (0xFFFFFFFFu << (shift + 8));
            // warp-aggregated histogram (match_any), uniform loop bound
            for (int p = tid; p < PPAD; p += TPB_POST) {
                const bool v = p < PP;
                const unsigned bits = v ? __float_as_uint(s_lm[p]) : 0u;
                const int bin = (bits >> shift) & 255;
                const bool pred = v && ((bits & hm) == pref);
                unsigned m = __match_any_sync(0xFFFFFFFFu, bin) &
                             __ballot_sync(0xFFFFFFFFu, pred);
                if (pred && lane == (__ffs(m) - 1))
                    atomicAdd(&s_hist[bin], __popc(m));
            }
            __syncthreads();
            if (tid < 256) s_cum[tid] = s_hist[tid];
            __syncthreads();
            for (int off = 1; off < 256; off <<= 1) {
                int v2 = 0;
                if (tid < 256 && tid + off < 256) v2 = s_cum[tid + off];
                __syncthreads();
                if (tid < 256) s_cum[tid] += v2;
                __syncthreads();
            }
            if (tid < 256) {
                const int above = (tid == 255) ? 0 : s_cum[tid + 1];
                if (s_cum[tid] >= rem && above < rem) {
                    s_prefix = pref | ((unsigned)tid << shift);
                    s_rem = rem - above;
                }
                s_hist[tid] = 0;   // re-zero for next pass
            }
            __syncthreads();
        }
        const unsigned t = s_prefix;
        float sumgt = 0.0f;
        int cntgt = 0;
        for (int p = tid; p < PP; p += TPB_POST) {
            const float lm = s_lm[p];
            if (__float_as_uint(lm) > t) { sumgt += lm; cntgt++; }
        }
        s_redf[tid] = sumgt;
        s_redi[tid] = cntgt;
        __syncthreads();
        for (int s = TPB_POST / 2; s > 0; s >>= 1) {
            if (tid < s) { s_redf[tid] += s_redf[tid + s]; s_redi[tid] += s_redi[tid + s]; }
            __syncthreads();
        }
        T = s_redf[0] + (float)(k - s_redi[0]) * __uint_as_float(t);
    }
    if (tid == 0)
        g_loss_c[b] = s_spos + T;
}

// ---------------- kernel 3: finalize ----------------
__global__ void k_final(float* __restrict__ out) {
    const int tid = threadIdx.x;
    __shared__ float s_l[64], s_c2[64];
    __shared__ int s_n[64];
    s_l[tid] = g_loss_l[tid];
    s_c2[tid] = g_loss_c[tid];
    s_n[tid] = g_num_pos[tid];
    __syncthreads();
    for (int s = 32; s > 0; s >>= 1) {
        if (tid < s) {
            s_l[tid] += s_l[tid + s];
            s_c2[tid] += s_c2[tid + s];
            s_n[tid] += s_n[tid + s];
        }
        __syncthreads();
    }
    if (tid == 0) {
        float n = fmaxf((float)s_n[0], 1.0f);
        out[0] = s_l[0] / n;
        out[1] = s_c2[0] / n;
    }
}

extern "C" void kernel_launch(void* const* d_in, const int* in_sizes, int n_in,
                              void* d_out, int out_size) {
    const float* loc = (const float*)d_in[0];
    const float* conf = (const float*)d_in[1];
    const float* priors = (const float*)d_in[2];
    const float* targets = (const float*)d_in[3];
    float* out = (float*)d_out;

    const int dynsz = 2 * ROWS * CC * 4;   // 82944 B
    cudaFuncSetAttribute(k_big, cudaFuncAttributeMaxDynamicSharedMemorySize, dynsz);

    k_big<<<NCE + MBLK, 128, dynsz>>>(conf, priors, targets);
    k_post<<<BN, TPB_POST>>>(conf, loc, priors, targets);
    k_final<<<1, 64>>>(out);
}